// round 15
// baseline (speedup 1.0000x reference)
#include <cuda_runtime.h>
#include <cuda_fp16.h>
#include <math.h>
#include <stdint.h>

// ---------------------------------------------------------------------------
// Problem constants
// ---------------------------------------------------------------------------
#define NTOK 32768
#define TOKD 1024
#define HIDD 1024
#define SEND 256
#define KC   512

// d_out float offsets (flattened reference tuple, fp32)
#define CENT_OFF 0
#define SE_OFF   131072
#define WC_OFF   16908288
#define SCL_OFF  16973824
#define OT_OFF   17039360
#define CT_OFF   17072128
#define OI_OFF   17072640
#define CI_OFF   17105408

#define SCALE_A 16.0f
#define SCALE_B 64.0f
#define OSCALE  (1.0f / 1024.0f)

#define ASLAB ((size_t)NTOK * HIDD)      // per-modal activation slab (elements)

// ---------------------------------------------------------------------------
// Scratch (device globals)
// ---------------------------------------------------------------------------
__device__ half  g_xh1[2][ASLAB];
__device__ half  g_xl1[2][ASLAB];
__device__ half  g_xh2[2][ASLAB];
__device__ half  g_xl2[2][ASLAB];
__device__ half  g_w1h[2][(size_t)HIDD * HIDD];   // transposed weights, N-major
__device__ half  g_w1l[2][(size_t)HIDD * HIDD];
__device__ half  g_w2h[2][(size_t)HIDD * HIDD];
__device__ half  g_w2l[2][(size_t)HIDD * HIDD];
__device__ half  g_w3h[2][(size_t)SEND * HIDD];
__device__ half  g_w3l[2][(size_t)SEND * HIDD];
__device__ half  g_ch[(size_t)KC * SEND];         // centroids hi (x64)
__device__ half  g_cl[(size_t)KC * SEND];         // centroids lo
__device__ float g_c2[KC];
__device__ float g_e2p[8 * NTOK];                 // [plane(4)][modal(2)][NTOK]
__device__ int   g_sc[2 * NTOK];
__device__ int   g_counts[2 * KC];
__device__ int   g_offsets[2 * KC];

// ---------------------------------------------------------------------------
// PTX helpers (sm_80-era, portable under compute_100)
// ---------------------------------------------------------------------------
__device__ __forceinline__ uint32_t smem_u32(const void* p) {
    uint32_t a;
    asm("{ .reg .u64 t; cvta.to.shared.u64 t, %1; cvt.u32.u64 %0, t; }"
        : "=r"(a) : "l"(p));
    return a;
}

#define MMA16816(d, a, b) \
    asm volatile( \
        "mma.sync.aligned.m16n8k16.row.col.f32.f16.f16.f32 " \
        "{%0,%1,%2,%3}, {%4,%5,%6,%7}, {%8,%9}, {%0,%1,%2,%3};" \
        : "+f"((d)[0]), "+f"((d)[1]), "+f"((d)[2]), "+f"((d)[3]) \
        : "r"((a)[0]), "r"((a)[1]), "r"((a)[2]), "r"((a)[3]), \
          "r"((b)[0]), "r"((b)[1]))

#define LDMX4(r0, r1, r2, r3, addr) \
    asm volatile("ldmatrix.sync.aligned.m8n8.x4.shared.b16 {%0,%1,%2,%3}, [%4];" \
        : "=r"(r0), "=r"(r1), "=r"(r2), "=r"(r3) : "r"(addr))

#define CPA16(dst, src) \
    asm volatile("cp.async.ca.shared.global [%0], [%1], 16;" :: "r"(dst), "l"(src))
#define CPA_COMMIT() asm volatile("cp.async.commit_group;")
#define CPA_WAIT0()  asm volatile("cp.async.wait_group 0;")

__device__ __forceinline__ void split2(float f, half& h, half& l) {
    h = __float2half_rn(f);
    l = __float2half_rn(f - __half2float(h));
}

// ---------------------------------------------------------------------------
// fp16x3 split-GEMM. CTA tile 128x64, 8 warps as 4x2 of 32x32 microtiles,
// 3 CTAs/SM (__launch_bounds__(256,3), 60KB smem, <=85 regs) for latency
// hiding. Single-sync 2-stage cp.async pipeline; group order ah*bh, ah*bl,
// al*bh preserved -> per-output accumulation order unchanged.
// OMODE: 1 = split out; 2 = fp32 out + split out + e2 partials (4 planes).
// ---------------------------------------------------------------------------
#define A_TILE_B  10240         // 128 rows * 80 B
#define B_TILE_B  5120          //  64 rows * 80 B
#define S_AH      0
#define S_AL      10240
#define S_BH      20480
#define S_BL      25600
#define STAGE_B   30720
#define GEMM_SMEM 61440         // 2 stages

template<int OMODE>
__global__ __launch_bounds__(256, 3)
void gemm_split(const half* __restrict__ AhG, const half* __restrict__ AlG,
                size_t aStr,
                const half* __restrict__ BhG, const half* __restrict__ BlG,
                size_t bStr,
                float* __restrict__ CfG, size_t cfStr,
                half* __restrict__ CohG, half* __restrict__ ColG, size_t coStr,
                float* __restrict__ E2p,
                int Kdim, int Mcols)
{
    extern __shared__ __align__(16) char smem[];
    const uint32_t sb0 = smem_u32(smem);

    const int z = blockIdx.z;
    const half* Ah = AhG + (size_t)z * aStr;
    const half* Al = AlG + (size_t)z * aStr;
    const half* Bh = BhG + (size_t)z * bStr;
    const half* Bl = BlG + (size_t)z * bStr;

    const int tid  = threadIdx.x;
    const int lane = tid & 31, wid = tid >> 5;
    const int warpRow = wid & 3;            // 0..3 -> 32-row band
    const int warpCol = wid >> 2;           // 0..1 -> 32-col band
    const int g = lane >> 2, tig = lane & 3;
    const int blockRow = blockIdx.y << 7;
    const int blockCol = blockIdx.x << 6;

    float acc[32];
#pragma unroll
    for (int i = 0; i < 32; ++i) acc[i] = 0.0f;

    const int fr = tid >> 1;
    const int fb = (tid & 1) << 1;
    const half* srcA  = Ah + (size_t)(blockRow + fr) * Kdim + fb * 8;
    const half* srcAl = Al + (size_t)(blockRow + fr) * Kdim + fb * 8;
    const half* srcB  = Bh + (size_t)(blockCol + (fr & 63)) * Kdim + fb * 8;
    const half* srcBl = Bl + (size_t)(blockCol + (fr & 63)) * Kdim + fb * 8;
    const uint32_t dstBase = sb0 + fr * 80 + fb * 16;

    const uint32_t loff = (uint32_t)(((lane & 7) + ((lane >> 3) & 1) * 8) * 80
                                     + ((lane >> 4) & 1) * 16);

    const int chunks = Kdim >> 5;

    auto ISSUE = [&](int c) {
        const int s = c & 1;
        const int kh = c << 5;
        uint32_t d = dstBase + s * STAGE_B;
        CPA16(d,            srcA + kh);  CPA16(d + 16,            srcA + kh + 8);
        CPA16(d + S_AL,     srcAl + kh); CPA16(d + S_AL + 16,     srcAl + kh + 8);
        if (tid < 128) {
            CPA16(d + S_BH, srcB + kh);  CPA16(d + S_BH + 16,     srcB + kh + 8);
            CPA16(d + S_BL, srcBl + kh); CPA16(d + S_BL + 16,     srcBl + kh + 8);
        }
    };

    auto COMPUTE = [&](int s) {
        const uint32_t base  = sb0 + s * STAGE_B;
        const uint32_t aBase = base + (warpRow * 32) * 80 + loff;
        const uint32_t bBase = base + S_BH + (warpCol * 32) * 80 + loff;
#pragma unroll
        for (int ks = 0; ks < 2; ++ks) {
            const uint32_t kof = ks << 5;
            uint32_t ah[2][4], al[2][4], bh[4][2], bl[4][2];
            // -- load ah + bh, run group 1 (ah*bh)
#pragma unroll
            for (int mt = 0; mt < 2; ++mt)
                LDMX4(ah[mt][0], ah[mt][1], ah[mt][2], ah[mt][3],
                      aBase + mt * (16 * 80) + kof);
#pragma unroll
            for (int p = 0; p < 2; ++p) {
                uint32_t r0, r1, r2, r3;
                LDMX4(r0, r1, r2, r3, bBase + p * (16 * 80) + kof);
                bh[2 * p][0] = r0; bh[2 * p + 1][0] = r1;
                bh[2 * p][1] = r2; bh[2 * p + 1][1] = r3;
            }
#pragma unroll
            for (int mt = 0; mt < 2; ++mt)
#pragma unroll
                for (int nt = 0; nt < 4; ++nt)
                    MMA16816(&acc[(mt * 4 + nt) * 4], ah[mt], bh[nt]);
            // -- load bl, run group 2 (ah*bl)
#pragma unroll
            for (int p = 0; p < 2; ++p) {
                uint32_t r0, r1, r2, r3;
                LDMX4(r0, r1, r2, r3, bBase + p * (16 * 80) + kof + (S_BL - S_BH));
                bl[2 * p][0] = r0; bl[2 * p + 1][0] = r1;
                bl[2 * p][1] = r2; bl[2 * p + 1][1] = r3;
            }
#pragma unroll
            for (int mt = 0; mt < 2; ++mt)
#pragma unroll
                for (int nt = 0; nt < 4; ++nt)
                    MMA16816(&acc[(mt * 4 + nt) * 4], ah[mt], bl[nt]);
            // -- load al, run group 3 (al*bh)
#pragma unroll
            for (int mt = 0; mt < 2; ++mt)
                LDMX4(al[mt][0], al[mt][1], al[mt][2], al[mt][3],
                      aBase + mt * (16 * 80) + kof + S_AL);
#pragma unroll
            for (int mt = 0; mt < 2; ++mt)
#pragma unroll
                for (int nt = 0; nt < 4; ++nt)
                    MMA16816(&acc[(mt * 4 + nt) * 4], al[mt], bh[nt]);
        }
    };

    ISSUE(0);
    CPA_COMMIT();
    for (int c = 0; c < chunks; ++c) {
        CPA_WAIT0();
        __syncthreads();          // chunk c visible; stage (c+1)&1 free
        if (c + 1 < chunks) {
            ISSUE(c + 1);
            CPA_COMMIT();
        }
        COMPUTE(c & 1);
    }
    __syncthreads();

    // ---- epilogue: stage fp32 acc in smem [128][68], transform + store
    float* cst = reinterpret_cast<float*>(smem);
#pragma unroll
    for (int mt = 0; mt < 2; ++mt)
#pragma unroll
        for (int nt = 0; nt < 4; ++nt) {
            const float* a4 = &acc[(mt * 4 + nt) * 4];
            int r0 = warpRow * 32 + (mt << 4) + g;
            int cc = warpCol * 32 + (nt << 3) + (tig << 1);
            *reinterpret_cast<float2*>(cst + r0 * 68 + cc) =
                make_float2(a4[0], a4[1]);
            *reinterpret_cast<float2*>(cst + (r0 + 8) * 68 + cc) =
                make_float2(a4[2], a4[3]);
        }
    __syncthreads();
    {
        half*  Coh = CohG + (size_t)z * coStr;
        half*  Col = ColG + (size_t)z * coStr;
        const int row  = tid >> 1;
        const int colh = (tid & 1) << 5;       // 0 / 32
        const float* src = cst + row * 68 + colh;
        const size_t gb = (size_t)(blockRow + row) * Mcols + blockCol + colh;
        float ss = 0.0f;
#pragma unroll
        for (int j = 0; j < 8; ++j) {
            float4 v = *reinterpret_cast<const float4*>(src + (j << 2));
            float t0 = tanhf(v.x * OSCALE), t1 = tanhf(v.y * OSCALE);
            float t2 = tanhf(v.z * OSCALE), t3 = tanhf(v.w * OSCALE);
            if (OMODE >= 1) {
                half h0, h1, h2, h3, l0, l1, l2, l3;
                split2(t0 * SCALE_A, h0, l0); split2(t1 * SCALE_A, h1, l1);
                split2(t2 * SCALE_A, h2, l2); split2(t3 * SCALE_A, h3, l3);
                half2 ph0 = __halves2half2(h0, h1), ph1 = __halves2half2(h2, h3);
                half2 pl0 = __halves2half2(l0, l1), pl1 = __halves2half2(l2, l3);
                uint2 uh, ul;
                uh.x = reinterpret_cast<uint32_t&>(ph0);
                uh.y = reinterpret_cast<uint32_t&>(ph1);
                ul.x = reinterpret_cast<uint32_t&>(pl0);
                ul.y = reinterpret_cast<uint32_t&>(pl1);
                *reinterpret_cast<uint2*>(Coh + gb + (j << 2)) = uh;
                *reinterpret_cast<uint2*>(Col + gb + (j << 2)) = ul;
            }
            if (OMODE == 2) {
                ss = fmaf(t0, t0, ss); ss = fmaf(t1, t1, ss);
                ss = fmaf(t2, t2, ss); ss = fmaf(t3, t3, ss);
                float4 o; o.x = t0; o.y = t1; o.z = t2; o.w = t3;
                *reinterpret_cast<float4*>(CfG + (size_t)z * cfStr + gb + (j << 2)) = o;
            }
        }
        if (OMODE == 2) {
            float* e2s = reinterpret_cast<float*>(smem) + 8704;   // past cst
            e2s[tid] = ss;
            __syncthreads();
            if ((tid & 1) == 0)
                E2p[(size_t)blockIdx.x * (2 * NTOK) + (size_t)z * NTOK
                    + blockRow + (tid >> 1)] = e2s[tid] + e2s[tid + 1];
        }
    }
}

// ---------------------------------------------------------------------------
// Tensor-core assignment, both modals (y = modal); fused count.
// (unchanged from round 14 except e2 partial sum over 4 planes)
// ---------------------------------------------------------------------------
#define ATILE_B    10240
#define ASTAGE_B   40960        // Ah | Al | Bh | Bl tiles (128-row, pitch 80)
#define ASSIGN_SMEM 81920

__global__ __launch_bounds__(256)
void assign_mma(const half* __restrict__ ShG, const half* __restrict__ SlG)
{
    extern __shared__ __align__(16) char smem[];
    const uint32_t sb0 = smem_u32(smem);
    const int modal = blockIdx.y;
    const half* Sh = ShG + (size_t)modal * ASLAB;
    const half* Sl = SlG + (size_t)modal * ASLAB;

    const int tid  = threadIdx.x;
    const int lane = tid & 31, wid = tid >> 5;
    const int warpRow = wid >> 2, warpCol = wid & 3;
    const int g = lane >> 2, tig = lane & 3;
    const int rowBase = blockIdx.x << 7;

    const int fr = tid >> 1, fb = (tid & 1) << 1;
    const half* pAh = Sh + (size_t)(rowBase + fr) * SEND + fb * 8;
    const half* pAl = Sl + (size_t)(rowBase + fr) * SEND + fb * 8;
    const uint32_t dAB = sb0 + fr * 80 + fb * 16;

    const uint32_t loff = (uint32_t)(((lane & 7) + ((lane >> 3) & 1) * 8) * 80
                                     + ((lane >> 4) & 1) * 16);

    float e2r[8];
#pragma unroll
    for (int mt = 0; mt < 4; ++mt)
#pragma unroll
        for (int h = 0; h < 2; ++h) {
            int idx = modal * NTOK + rowBase + warpRow * 64 + mt * 16 + g + h * 8;
            e2r[mt * 2 + h] = ((g_e2p[idx] + g_e2p[2 * NTOK + idx])
                             + g_e2p[4 * NTOK + idx]) + g_e2p[6 * NTOK + idx];
        }

    float bestV[8]; int bestI[8];
#pragma unroll
    for (int i = 0; i < 8; ++i) { bestV[i] = 3.4e38f; bestI[i] = 0; }

    float acc[64];
#pragma unroll
    for (int i = 0; i < 64; ++i) acc[i] = 0.0f;

    auto ISSUE = [&](int t) {
        const int ct = t >> 3, c = t & 7;
        const int kh = c << 5;
        uint32_t d = dAB + (uint32_t)(t & 1) * ASTAGE_B;
        CPA16(d,               pAh + kh); CPA16(d + 16,               pAh + kh + 8);
        CPA16(d + ATILE_B,     pAl + kh); CPA16(d + ATILE_B + 16,     pAl + kh + 8);
        const half* pBh = g_ch + (size_t)(ct * 128 + fr) * SEND + fb * 8 + kh;
        const half* pBl = g_cl + (size_t)(ct * 128 + fr) * SEND + fb * 8 + kh;
        CPA16(d + 2 * ATILE_B, pBh);      CPA16(d + 2 * ATILE_B + 16, pBh + 8);
        CPA16(d + 3 * ATILE_B, pBl);      CPA16(d + 3 * ATILE_B + 16, pBl + 8);
    };

    auto COMPUTE = [&](int s) {
        const uint32_t base  = sb0 + s * ASTAGE_B;
        const uint32_t aBase = base + (warpRow * 64) * 80 + loff;
        const uint32_t bBase = base + 2 * ATILE_B + (warpCol * 32) * 80 + loff;
#pragma unroll
        for (int ks = 0; ks < 2; ++ks) {
            const uint32_t kof = ks << 5;
            uint32_t ah[4][4], al[4][4], bh[4][2], bl[4][2];
#pragma unroll
            for (int mt = 0; mt < 4; ++mt)
                LDMX4(ah[mt][0], ah[mt][1], ah[mt][2], ah[mt][3],
                      aBase + mt * (16 * 80) + kof);
#pragma unroll
            for (int p = 0; p < 2; ++p) {
                uint32_t r0, r1, r2, r3;
                LDMX4(r0, r1, r2, r3, bBase + p * (16 * 80) + kof);
                bh[2 * p][0] = r0; bh[2 * p + 1][0] = r1;
                bh[2 * p][1] = r2; bh[2 * p + 1][1] = r3;
            }
#pragma unroll
            for (int mt = 0; mt < 4; ++mt)
#pragma unroll
                for (int nt = 0; nt < 4; ++nt)
                    MMA16816(&acc[(mt * 4 + nt) * 4], ah[mt], bh[nt]);
#pragma unroll
            for (int p = 0; p < 2; ++p) {
                uint32_t r0, r1, r2, r3;
                LDMX4(r0, r1, r2, r3, bBase + p * (16 * 80) + kof + ATILE_B);
                bl[2 * p][0] = r0; bl[2 * p + 1][0] = r1;
                bl[2 * p][1] = r2; bl[2 * p + 1][1] = r3;
            }
#pragma unroll
            for (int mt = 0; mt < 4; ++mt)
#pragma unroll
                for (int nt = 0; nt < 4; ++nt)
                    MMA16816(&acc[(mt * 4 + nt) * 4], ah[mt], bl[nt]);
#pragma unroll
            for (int mt = 0; mt < 4; ++mt)
                LDMX4(al[mt][0], al[mt][1], al[mt][2], al[mt][3],
                      aBase + mt * (16 * 80) + kof + ATILE_B);
#pragma unroll
            for (int mt = 0; mt < 4; ++mt)
#pragma unroll
                for (int nt = 0; nt < 4; ++nt)
                    MMA16816(&acc[(mt * 4 + nt) * 4], al[mt], bh[nt]);
        }
    };

    ISSUE(0);
    CPA_COMMIT();
    for (int t = 0; t < 32; ++t) {
        CPA_WAIT0();
        __syncthreads();
        if (t + 1 < 32) {
            ISSUE(t + 1);
            CPA_COMMIT();
        }
        COMPUTE(t & 1);

        if ((t & 7) == 7) {               // registers + const global only
            const int ct = t >> 3;
#pragma unroll
            for (int nt = 0; nt < 4; ++nt)
#pragma unroll
                for (int j = 0; j < 2; ++j) {
                    int col = ct * 128 + warpCol * 32 + nt * 8 + tig * 2 + j;
                    float c2v = g_c2[col];
#pragma unroll
                    for (int mt = 0; mt < 4; ++mt)
#pragma unroll
                        for (int h = 0; h < 2; ++h) {
                            float s = (c2v + e2r[mt * 2 + h]) -
                                2.0f * (acc[(mt * 4 + nt) * 4 + h * 2 + j] * OSCALE);
                            int bi = mt * 2 + h;
                            if (s < bestV[bi] ||
                                (s == bestV[bi] && col < bestI[bi])) {
                                bestV[bi] = s; bestI[bi] = col;
                            }
                        }
                }
#pragma unroll
            for (int i = 0; i < 64; ++i) acc[i] = 0.0f;
        }
    }
    __syncthreads();

    // ---- cross-thread reduction (16 slots per row) + fused count
    float (*rv)[16] = reinterpret_cast<float(*)[16]>(smem);
    int   (*ri)[16] = reinterpret_cast<int(*)[16]>(smem + 8192);
    const int slot = warpCol * 4 + tig;
#pragma unroll
    for (int mt = 0; mt < 4; ++mt)
#pragma unroll
        for (int h = 0; h < 2; ++h) {
            int row = warpRow * 64 + mt * 16 + g + h * 8;
            rv[row][slot] = bestV[mt * 2 + h];
            ri[row][slot] = bestI[mt * 2 + h];
        }
    __syncthreads();
    if (tid < 128) {
        float bv = rv[tid][0]; int bi = ri[tid][0];
#pragma unroll
        for (int u = 1; u < 16; ++u) {
            float v = rv[tid][u]; int ix = ri[tid][u];
            if (v < bv || (v == bv && ix < bi)) { bv = v; bi = ix; }
        }
        g_sc[modal * NTOK + rowBase + tid] = bi;
        atomicAdd(&g_counts[modal * KC + bi], 1);
    }
}

// ---------------------------------------------------------------------------
// emb fp32 -> (hi, lo) halves, scaled — both modals (y = modal)
// ---------------------------------------------------------------------------
__global__ void split_src(const float* __restrict__ X0,
                          const float* __restrict__ X1,
                          half* __restrict__ XhG, half* __restrict__ XlG)
{
    const int m = blockIdx.y;
    const float* X = m ? X1 : X0;
    half* Xh = XhG + (size_t)m * ASLAB;
    half* Xl = XlG + (size_t)m * ASLAB;
    int i = blockIdx.x * blockDim.x + threadIdx.x;
    float4 v = reinterpret_cast<const float4*>(X)[i];
    half h0, h1, h2, h3, l0, l1, l2, l3;
    split2(v.x * SCALE_A, h0, l0); split2(v.y * SCALE_A, h1, l1);
    split2(v.z * SCALE_A, h2, l2); split2(v.w * SCALE_A, h3, l3);
    half2 ph0 = __halves2half2(h0, h1), ph1 = __halves2half2(h2, h3);
    half2 pl0 = __halves2half2(l0, l1), pl1 = __halves2half2(l2, l3);
    uint2 uh, ul;
    uh.x = reinterpret_cast<uint32_t&>(ph0); uh.y = reinterpret_cast<uint32_t&>(ph1);
    ul.x = reinterpret_cast<uint32_t&>(pl0); ul.y = reinterpret_cast<uint32_t&>(pl1);
    reinterpret_cast<uint2*>(Xh)[i] = uh;
    reinterpret_cast<uint2*>(Xl)[i] = ul;
}

// ---------------------------------------------------------------------------
// All 6 weight transposes + splits in one launch.
// ---------------------------------------------------------------------------
__global__ void transpose_split_all(
    const float* __restrict__ W10, const float* __restrict__ W20,
    const float* __restrict__ W30, const float* __restrict__ W11,
    const float* __restrict__ W21, const float* __restrict__ W31)
{
    const int z = blockIdx.z;
    const int m = z / 3, layer = z % 3;
    const int N = (layer == 2) ? SEND : HIDD;
    if ((blockIdx.x << 5) >= N) return;

    const float* W =
        (layer == 0) ? (m ? W11 : W10) :
        (layer == 1) ? (m ? W21 : W20) : (m ? W31 : W30);
    half* Th = (layer == 0) ? g_w1h[m] : (layer == 1) ? g_w2h[m] : g_w3h[m];
    half* Tl = (layer == 0) ? g_w1l[m] : (layer == 1) ? g_w2l[m] : g_w3l[m];

    __shared__ float t[32][33];
    const int bx = blockIdx.x << 5;   // n base
    const int by = blockIdx.y << 5;   // k base
#pragma unroll
    for (int j = 0; j < 32; j += 8)
        t[threadIdx.y + j][threadIdx.x] =
            W[(size_t)(by + threadIdx.y + j) * N + bx + threadIdx.x];
    __syncthreads();
#pragma unroll
    for (int j = 0; j < 32; j += 8) {
        float f = t[threadIdx.x][threadIdx.y + j] * SCALE_B;
        half h, l;
        split2(f, h, l);
        size_t o = (size_t)(bx + threadIdx.y + j) * HIDD + by + threadIdx.x;
        Th[o] = h;
        Tl[o] = l;
    }
}

// ---------------------------------------------------------------------------
// Fused centroid prep: tanh -> d_out, split halves, c2 sumsq, zero counts.
// ---------------------------------------------------------------------------
__global__ void centroid_prep(const float* __restrict__ raw, float* __restrict__ out)
{
    const int tid  = threadIdx.x;
    const int lane = tid & 31;
    const int row  = blockIdx.x * 8 + (tid >> 5);
    const int gtid = blockIdx.x * 256 + tid;
    if (gtid < 2 * KC) g_counts[gtid] = 0;

    const float* src = raw + (size_t)row * SEND;
    float ss = 0.0f;
#pragma unroll
    for (int j = 0; j < 8; ++j) {
        int idx = lane + j * 32;
        float t = tanhf(src[idx]);
        out[CENT_OFF + (size_t)row * SEND + idx] = t;
        half h, l;
        split2(t * SCALE_B, h, l);
        g_ch[(size_t)row * SEND + idx] = h;
        g_cl[(size_t)row * SEND + idx] = l;
        ss = fmaf(t, t, ss);
    }
#pragma unroll
    for (int o = 16; o > 0; o >>= 1) ss += __shfl_xor_sync(0xffffffffu, ss, o);
    if (lane == 0) g_c2[row] = ss;
}

// ---------------------------------------------------------------------------
// Counting sort (stable) — both modals per launch
// ---------------------------------------------------------------------------
__global__ void scan_kernel()
{
    __shared__ int tmp[KC];
    const int modal = blockIdx.x;
    int t = threadIdx.x;
    int v = g_counts[modal * KC + t];
    tmp[t] = v;
    __syncthreads();
    for (int off = 1; off < KC; off <<= 1) {
        int x = (t >= off) ? tmp[t - off] : 0;
        __syncthreads();
        tmp[t] += x;
        __syncthreads();
    }
    g_offsets[modal * KC + t] = tmp[t] - v;
}

__global__ void scatter_kernel(float* __restrict__ out)
{
    const int k = blockIdx.x;
    const int modal = blockIdx.y;
    float* order = out + (modal ? OI_OFF : OT_OFF);
    const int base0 = modal * NTOK;
    __shared__ int warpTot[8];
    int base = g_offsets[modal * KC + k];
    int lane = threadIdx.x & 31, wid = threadIdx.x >> 5;

    for (int start = 0; start < NTOK; start += 256) {
        int i = start + threadIdx.x;
        bool m = (g_sc[base0 + i] == k);
        unsigned b = __ballot_sync(0xffffffffu, m);
        if (lane == 0) warpTot[wid] = __popc(b);
        __syncthreads();
        int woff = 0, tot = 0;
#pragma unroll
        for (int w = 0; w < 8; ++w) { int c = warpTot[w]; tot += c; if (w < wid) woff += c; }
        if (m) order[base + woff + __popc(b & ((1u << lane) - 1u))] = (float)i;
        base += tot;
        __syncthreads();
    }
}

// ---------------------------------------------------------------------------
// word_class / sense_class / counts (fused)
// ---------------------------------------------------------------------------
__global__ void finalize_kernel(float* __restrict__ out)
{
    int i = blockIdx.x * blockDim.x + threadIdx.x;
    out[WC_OFF + i]  = (i < NTOK) ? 0.0f : 1.0f;
    out[SCL_OFF + i] = (float)g_sc[i];
    if (i < 2 * KC) {
        int m = i >> 9, k = i & 511;
        out[(m ? CI_OFF : CT_OFF) + k] = (float)g_counts[i];
    }
}

// ---------------------------------------------------------------------------
// Launch
// ---------------------------------------------------------------------------
extern "C" void kernel_launch(void* const* d_in, const int* in_sizes, int n_in,
                              void* d_out, int out_size)
{
    const float* emb[2] = { (const float*)d_in[0], (const float*)d_in[1] };
    const float* W1[2]  = { (const float*)d_in[2], (const float*)d_in[5] };
    const float* W2[2]  = { (const float*)d_in[3], (const float*)d_in[6] };
    const float* W3[2]  = { (const float*)d_in[4], (const float*)d_in[7] };
    const float* craw   = (const float*)d_in[8];
    float* out = (float*)d_out;

    half *xh1, *xl1, *xh2, *xl2;
    half *w1h, *w1l, *w2h, *w2l, *w3h, *w3l;
    float* e2p;
    cudaGetSymbolAddress((void**)&xh1, g_xh1);
    cudaGetSymbolAddress((void**)&xl1, g_xl1);
    cudaGetSymbolAddress((void**)&xh2, g_xh2);
    cudaGetSymbolAddress((void**)&xl2, g_xl2);
    cudaGetSymbolAddress((void**)&w1h, g_w1h);
    cudaGetSymbolAddress((void**)&w1l, g_w1l);
    cudaGetSymbolAddress((void**)&w2h, g_w2h);
    cudaGetSymbolAddress((void**)&w2l, g_w2l);
    cudaGetSymbolAddress((void**)&w3h, g_w3h);
    cudaGetSymbolAddress((void**)&w3l, g_w3l);
    cudaGetSymbolAddress((void**)&e2p, g_e2p);

    cudaFuncSetAttribute(gemm_split<1>,
                         cudaFuncAttributeMaxDynamicSharedMemorySize, GEMM_SMEM);
    cudaFuncSetAttribute(gemm_split<2>,
                         cudaFuncAttributeMaxDynamicSharedMemorySize, GEMM_SMEM);
    cudaFuncSetAttribute(assign_mma,
                         cudaFuncAttributeMaxDynamicSharedMemorySize, ASSIGN_SMEM);

    const size_t WSZ  = (size_t)HIDD * HIDD;
    const size_t W3SZ = (size_t)SEND * HIDD;

    centroid_prep<<<KC / 8, 256>>>(craw, out);
    transpose_split_all<<<dim3(32, 32, 6), dim3(32, 8)>>>(
        W1[0], W2[0], W3[0], W1[1], W2[1], W3[1]);

    split_src<<<dim3((NTOK * TOKD / 4) / 256, 2), 256>>>(emb[0], emb[1], xh1, xl1);

    // L1: xh1 -> xh2 (both modals)
    gemm_split<1><<<dim3(HIDD / 64, NTOK / 128, 2), 256, GEMM_SMEM>>>(
        xh1, xl1, ASLAB, w1h, w1l, WSZ,
        nullptr, 0, xh2, xl2, ASLAB, nullptr, TOKD, HIDD);

    // L2: xh2 -> xh1
    gemm_split<1><<<dim3(HIDD / 64, NTOK / 128, 2), 256, GEMM_SMEM>>>(
        xh2, xl2, ASLAB, w2h, w2l, WSZ,
        nullptr, 0, xh1, xl1, ASLAB, nullptr, HIDD, HIDD);

    // L3: xh1 -> se (fp32) + xh2 (split) + e2 partials (4 planes)
    gemm_split<2><<<dim3(SEND / 64, NTOK / 128, 2), 256, GEMM_SMEM>>>(
        xh1, xl1, ASLAB, w3h, w3l, W3SZ,
        out + SE_OFF, (size_t)NTOK * SEND, xh2, xl2, ASLAB, e2p, HIDD, SEND);

    assign_mma<<<dim3(NTOK / 128, 2), 256, ASSIGN_SMEM>>>(xh2, xl2);

    scan_kernel<<<2, KC>>>();
    scatter_kernel<<<dim3(KC, 2), 256>>>(out);

    finalize_kernel<<<(2 * NTOK) / 256, 256>>>(out);
}

// round 16
// speedup vs baseline: 1.0169x; 1.0169x over previous
#include <cuda_runtime.h>
#include <cuda_fp16.h>
#include <math.h>
#include <stdint.h>

// ---------------------------------------------------------------------------
// Problem constants
// ---------------------------------------------------------------------------
#define NTOK 32768
#define TOKD 1024
#define HIDD 1024
#define SEND 256
#define KC   512

// d_out float offsets (flattened reference tuple, fp32)
#define CENT_OFF 0
#define SE_OFF   131072
#define WC_OFF   16908288
#define SCL_OFF  16973824
#define OT_OFF   17039360
#define CT_OFF   17072128
#define OI_OFF   17072640
#define CI_OFF   17105408

#define SCALE_A 16.0f
#define SCALE_B 64.0f
#define OSCALE  (1.0f / 1024.0f)

#define ASLAB ((size_t)NTOK * HIDD)      // per-modal activation slab (elements)

// ---------------------------------------------------------------------------
// Scratch (device globals) — per-modal activation slabs for merged launches
// ---------------------------------------------------------------------------
__device__ half  g_xh1[2][ASLAB];
__device__ half  g_xl1[2][ASLAB];
__device__ half  g_xh2[2][ASLAB];
__device__ half  g_xl2[2][ASLAB];
__device__ half  g_w1h[2][(size_t)HIDD * HIDD];   // transposed weights, N-major
__device__ half  g_w1l[2][(size_t)HIDD * HIDD];
__device__ half  g_w2h[2][(size_t)HIDD * HIDD];
__device__ half  g_w2l[2][(size_t)HIDD * HIDD];
__device__ half  g_w3h[2][(size_t)SEND * HIDD];
__device__ half  g_w3l[2][(size_t)SEND * HIDD];
__device__ half  g_ch[(size_t)KC * SEND];         // centroids hi (x64)
__device__ half  g_cl[(size_t)KC * SEND];         // centroids lo
__device__ float g_c2[KC];
__device__ float g_e2p[4 * NTOK];                 // [plane(2)][modal(2)][NTOK]
__device__ int   g_sc[2 * NTOK];
__device__ int   g_counts[2 * KC];
__device__ int   g_offsets[2 * KC];

// ---------------------------------------------------------------------------
// PTX helpers (sm_80-era, portable under compute_100)
// ---------------------------------------------------------------------------
__device__ __forceinline__ uint32_t smem_u32(const void* p) {
    uint32_t a;
    asm("{ .reg .u64 t; cvta.to.shared.u64 t, %1; cvt.u32.u64 %0, t; }"
        : "=r"(a) : "l"(p));
    return a;
}

#define MMA16816(d, a, b) \
    asm volatile( \
        "mma.sync.aligned.m16n8k16.row.col.f32.f16.f16.f32 " \
        "{%0,%1,%2,%3}, {%4,%5,%6,%7}, {%8,%9}, {%0,%1,%2,%3};" \
        : "+f"((d)[0]), "+f"((d)[1]), "+f"((d)[2]), "+f"((d)[3]) \
        : "r"((a)[0]), "r"((a)[1]), "r"((a)[2]), "r"((a)[3]), \
          "r"((b)[0]), "r"((b)[1]))

#define LDMX4(r0, r1, r2, r3, addr) \
    asm volatile("ldmatrix.sync.aligned.m8n8.x4.shared.b16 {%0,%1,%2,%3}, [%4];" \
        : "=r"(r0), "=r"(r1), "=r"(r2), "=r"(r3) : "r"(addr))

// cp.async.cg: 16-byte global->shared, L2-only (bypasses L1 data path) —
// streaming operands are never re-read through L1, so skip the allocation.
#define CPA16(dst, src) \
    asm volatile("cp.async.cg.shared.global [%0], [%1], 16;" :: "r"(dst), "l"(src))
#define CPA_COMMIT() asm volatile("cp.async.commit_group;")
#define CPA_WAIT0()  asm volatile("cp.async.wait_group 0;")

__device__ __forceinline__ void split2(float f, half& h, half& l) {
    h = __float2half_rn(f);
    l = __float2half_rn(f - __half2float(h));
}

// ---------------------------------------------------------------------------
// fp16x3 split-GEMM, both modals per launch (z = modal).
// Single-sync mainloop; COMPUTE interleaves fragment loads with MMA groups
// (group order ah*bh, ah*bl, al*bh preserved -> bit-identical accumulation).
// OMODE: 1 = split (hi,lo)*SCALE_A out; 2 = fp32 out + split out + e2 partials.
// ---------------------------------------------------------------------------
#define TILE_B    10240         // 128 rows * 80 B
#define STAGE_B   40960         // Ah | Al | Bh | Bl tiles
#define GEMM_SMEM 81920         // 2 stages

template<int OMODE>
__global__ __launch_bounds__(256)
void gemm_split(const half* __restrict__ AhG, const half* __restrict__ AlG,
                size_t aStr,
                const half* __restrict__ BhG, const half* __restrict__ BlG,
                size_t bStr,
                float* __restrict__ CfG, size_t cfStr,
                half* __restrict__ CohG, half* __restrict__ ColG, size_t coStr,
                float* __restrict__ E2p,
                int Kdim, int Mcols)
{
    extern __shared__ __align__(16) char smem[];
    const uint32_t sb0 = smem_u32(smem);

    const int z = blockIdx.z;
    const half* Ah = AhG + (size_t)z * aStr;
    const half* Al = AlG + (size_t)z * aStr;
    const half* Bh = BhG + (size_t)z * bStr;
    const half* Bl = BlG + (size_t)z * bStr;

    const int tid  = threadIdx.x;
    const int lane = tid & 31, wid = tid >> 5;
    const int warpRow = wid >> 2;
    const int warpCol = wid & 3;
    const int g = lane >> 2, tig = lane & 3;
    const int blockRow = blockIdx.y << 7;
    const int blockCol = blockIdx.x << 7;

    float acc[64];
#pragma unroll
    for (int i = 0; i < 64; ++i) acc[i] = 0.0f;

    const int fr = tid >> 1;
    const int fb = (tid & 1) << 1;
    const half* srcA  = Ah + (size_t)(blockRow + fr) * Kdim + fb * 8;
    const half* srcAl = Al + (size_t)(blockRow + fr) * Kdim + fb * 8;
    const half* srcB  = Bh + (size_t)(blockCol + fr) * Kdim + fb * 8;
    const half* srcBl = Bl + (size_t)(blockCol + fr) * Kdim + fb * 8;
    const uint32_t dstBase = sb0 + fr * 80 + fb * 16;

    const uint32_t loff = (uint32_t)(((lane & 7) + ((lane >> 3) & 1) * 8) * 80
                                     + ((lane >> 4) & 1) * 16);

    const int chunks = Kdim >> 5;

    auto ISSUE = [&](int c) {
        const int s = c & 1;
        const int kh = c << 5;
        uint32_t d = dstBase + s * STAGE_B;
        CPA16(d,              srcA + kh);  CPA16(d + 16,              srcA + kh + 8);
        CPA16(d + TILE_B,     srcAl + kh); CPA16(d + TILE_B + 16,     srcAl + kh + 8);
        CPA16(d + 2 * TILE_B, srcB + kh);  CPA16(d + 2 * TILE_B + 16, srcB + kh + 8);
        CPA16(d + 3 * TILE_B, srcBl + kh); CPA16(d + 3 * TILE_B + 16, srcBl + kh + 8);
    };

    auto COMPUTE = [&](int s) {
        const uint32_t base  = sb0 + s * STAGE_B;
        const uint32_t aBase = base + (warpRow * 64) * 80 + loff;
        const uint32_t bBase = base + 2 * TILE_B + (warpCol * 32) * 80 + loff;
#pragma unroll
        for (int ks = 0; ks < 2; ++ks) {
            const uint32_t kof = ks << 5;
            uint32_t ah[4][4], al[4][4], bh[4][2], bl[4][2];
            // -- load ah + bh, run group 1 (ah*bh)
#pragma unroll
            for (int mt = 0; mt < 4; ++mt) {
                uint32_t ad = aBase + mt * (16 * 80) + kof;
                LDMX4(ah[mt][0], ah[mt][1], ah[mt][2], ah[mt][3], ad);
            }
#pragma unroll
            for (int p = 0; p < 2; ++p) {
                uint32_t bd = bBase + p * (16 * 80) + kof;
                uint32_t r0, r1, r2, r3;
                LDMX4(r0, r1, r2, r3, bd);
                bh[2 * p][0] = r0; bh[2 * p + 1][0] = r1;
                bh[2 * p][1] = r2; bh[2 * p + 1][1] = r3;
            }
#pragma unroll
            for (int mt = 0; mt < 4; ++mt)
#pragma unroll
                for (int nt = 0; nt < 4; ++nt)
                    MMA16816(&acc[(mt * 4 + nt) * 4], ah[mt], bh[nt]);
            // -- load bl, run group 2 (ah*bl)
#pragma unroll
            for (int p = 0; p < 2; ++p) {
                uint32_t bd = bBase + p * (16 * 80) + kof + TILE_B;
                uint32_t r0, r1, r2, r3;
                LDMX4(r0, r1, r2, r3, bd);
                bl[2 * p][0] = r0; bl[2 * p + 1][0] = r1;
                bl[2 * p][1] = r2; bl[2 * p + 1][1] = r3;
            }
#pragma unroll
            for (int mt = 0; mt < 4; ++mt)
#pragma unroll
                for (int nt = 0; nt < 4; ++nt)
                    MMA16816(&acc[(mt * 4 + nt) * 4], ah[mt], bl[nt]);
            // -- load al, run group 3 (al*bh)
#pragma unroll
            for (int mt = 0; mt < 4; ++mt) {
                uint32_t ad = aBase + mt * (16 * 80) + kof + TILE_B;
                LDMX4(al[mt][0], al[mt][1], al[mt][2], al[mt][3], ad);
            }
#pragma unroll
            for (int mt = 0; mt < 4; ++mt)
#pragma unroll
                for (int nt = 0; nt < 4; ++nt)
                    MMA16816(&acc[(mt * 4 + nt) * 4], al[mt], bh[nt]);
        }
    };

    ISSUE(0);
    CPA_COMMIT();
    for (int c = 0; c < chunks; ++c) {
        CPA_WAIT0();
        __syncthreads();          // chunk c visible; stage (c+1)&1 free
        if (c + 1 < chunks) {
            ISSUE(c + 1);
            CPA_COMMIT();
        }
        COMPUTE(c & 1);
    }
    __syncthreads();

    // ---- epilogue: stage fp32 acc in smem, then coalesced transform+store
    float* cst = reinterpret_cast<float*>(smem);   // [128][132]
#pragma unroll
    for (int mt = 0; mt < 4; ++mt)
#pragma unroll
        for (int nt = 0; nt < 4; ++nt) {
            const float* a4 = &acc[(mt * 4 + nt) * 4];
            int r0 = (warpRow << 6) + (mt << 4) + g;
            int cc = (warpCol << 5) + (nt << 3) + (tig << 1);
            *reinterpret_cast<float2*>(cst + r0 * 132 + cc) =
                make_float2(a4[0], a4[1]);
            *reinterpret_cast<float2*>(cst + (r0 + 8) * 132 + cc) =
                make_float2(a4[2], a4[3]);
        }
    __syncthreads();
    {
        half*  Coh = CohG + (size_t)z * coStr;
        half*  Col = ColG + (size_t)z * coStr;
        const int row  = tid >> 1;
        const int colh = (tid & 1) << 6;
        const float* src = cst + row * 132 + colh;
        const size_t gb = (size_t)(blockRow + row) * Mcols + blockCol + colh;
        float ss = 0.0f;
#pragma unroll
        for (int j = 0; j < 16; ++j) {
            float4 v = *reinterpret_cast<const float4*>(src + (j << 2));
            float t0 = tanhf(v.x * OSCALE), t1 = tanhf(v.y * OSCALE);
            float t2 = tanhf(v.z * OSCALE), t3 = tanhf(v.w * OSCALE);
            if (OMODE >= 1) {
                half h0, h1, h2, h3, l0, l1, l2, l3;
                split2(t0 * SCALE_A, h0, l0); split2(t1 * SCALE_A, h1, l1);
                split2(t2 * SCALE_A, h2, l2); split2(t3 * SCALE_A, h3, l3);
                half2 ph0 = __halves2half2(h0, h1), ph1 = __halves2half2(h2, h3);
                half2 pl0 = __halves2half2(l0, l1), pl1 = __halves2half2(l2, l3);
                uint2 uh, ul;
                uh.x = reinterpret_cast<uint32_t&>(ph0);
                uh.y = reinterpret_cast<uint32_t&>(ph1);
                ul.x = reinterpret_cast<uint32_t&>(pl0);
                ul.y = reinterpret_cast<uint32_t&>(pl1);
                *reinterpret_cast<uint2*>(Coh + gb + (j << 2)) = uh;
                *reinterpret_cast<uint2*>(Col + gb + (j << 2)) = ul;
            }
            if (OMODE == 2) {
                ss = fmaf(t0, t0, ss); ss = fmaf(t1, t1, ss);
                ss = fmaf(t2, t2, ss); ss = fmaf(t3, t3, ss);
                float4 o; o.x = t0; o.y = t1; o.z = t2; o.w = t3;
                *reinterpret_cast<float4*>(CfG + (size_t)z * cfStr + gb + (j << 2)) = o;
            }
        }
        if (OMODE == 2) {
            float* e2s = reinterpret_cast<float*>(smem) + 16896;   // past cst
            e2s[tid] = ss;
            __syncthreads();
            if ((tid & 1) == 0)
                E2p[(size_t)blockIdx.x * (2 * NTOK) + (size_t)z * NTOK
                    + blockRow + (tid >> 1)] = e2s[tid] + e2s[tid + 1];
        }
    }
}

// ---------------------------------------------------------------------------
// Tensor-core assignment, both modals (y = modal); fused count.
// ---------------------------------------------------------------------------
#define ASSIGN_SMEM 81920

__global__ __launch_bounds__(256)
void assign_mma(const half* __restrict__ ShG, const half* __restrict__ SlG)
{
    extern __shared__ __align__(16) char smem[];
    const uint32_t sb0 = smem_u32(smem);
    const int modal = blockIdx.y;
    const half* Sh = ShG + (size_t)modal * ASLAB;
    const half* Sl = SlG + (size_t)modal * ASLAB;

    const int tid  = threadIdx.x;
    const int lane = tid & 31, wid = tid >> 5;
    const int warpRow = wid >> 2, warpCol = wid & 3;
    const int g = lane >> 2, tig = lane & 3;
    const int rowBase = blockIdx.x << 7;

    const int fr = tid >> 1, fb = (tid & 1) << 1;
    const half* pAh = Sh + (size_t)(rowBase + fr) * SEND + fb * 8;
    const half* pAl = Sl + (size_t)(rowBase + fr) * SEND + fb * 8;
    const uint32_t dAB = sb0 + fr * 80 + fb * 16;

    const uint32_t loff = (uint32_t)(((lane & 7) + ((lane >> 3) & 1) * 8) * 80
                                     + ((lane >> 4) & 1) * 16);

    float e2r[8];
#pragma unroll
    for (int mt = 0; mt < 4; ++mt)
#pragma unroll
        for (int h = 0; h < 2; ++h) {
            int idx = modal * NTOK + rowBase + warpRow * 64 + mt * 16 + g + h * 8;
            e2r[mt * 2 + h] = g_e2p[idx] + g_e2p[2 * NTOK + idx];
        }

    float bestV[8]; int bestI[8];
#pragma unroll
    for (int i = 0; i < 8; ++i) { bestV[i] = 3.4e38f; bestI[i] = 0; }

    float acc[64];
#pragma unroll
    for (int i = 0; i < 64; ++i) acc[i] = 0.0f;

    auto ISSUE = [&](int t) {
        const int ct = t >> 3, c = t & 7;
        const int kh = c << 5;
        uint32_t d = dAB + (uint32_t)(t & 1) * STAGE_B;
        CPA16(d,              pAh + kh); CPA16(d + 16,              pAh + kh + 8);
        CPA16(d + TILE_B,     pAl + kh); CPA16(d + TILE_B + 16,     pAl + kh + 8);
        const half* pBh = g_ch + (size_t)(ct * 128 + fr) * SEND + fb * 8 + kh;
        const half* pBl = g_cl + (size_t)(ct * 128 + fr) * SEND + fb * 8 + kh;
        CPA16(d + 2 * TILE_B, pBh);      CPA16(d + 2 * TILE_B + 16, pBh + 8);
        CPA16(d + 3 * TILE_B, pBl);      CPA16(d + 3 * TILE_B + 16, pBl + 8);
    };

    auto COMPUTE = [&](int s) {
        const uint32_t base  = sb0 + s * STAGE_B;
        const uint32_t aBase = base + (warpRow * 64) * 80 + loff;
        const uint32_t bBase = base + 2 * TILE_B + (warpCol * 32) * 80 + loff;
#pragma unroll
        for (int ks = 0; ks < 2; ++ks) {
            const uint32_t kof = ks << 5;
            uint32_t ah[4][4], al[4][4], bh[4][2], bl[4][2];
#pragma unroll
            for (int mt = 0; mt < 4; ++mt) {
                uint32_t ad = aBase + mt * (16 * 80) + kof;
                LDMX4(ah[mt][0], ah[mt][1], ah[mt][2], ah[mt][3], ad);
            }
#pragma unroll
            for (int p = 0; p < 2; ++p) {
                uint32_t bd = bBase + p * (16 * 80) + kof;
                uint32_t r0, r1, r2, r3;
                LDMX4(r0, r1, r2, r3, bd);
                bh[2 * p][0] = r0; bh[2 * p + 1][0] = r1;
                bh[2 * p][1] = r2; bh[2 * p + 1][1] = r3;
            }
#pragma unroll
            for (int mt = 0; mt < 4; ++mt)
#pragma unroll
                for (int nt = 0; nt < 4; ++nt)
                    MMA16816(&acc[(mt * 4 + nt) * 4], ah[mt], bh[nt]);
#pragma unroll
            for (int p = 0; p < 2; ++p) {
                uint32_t bd = bBase + p * (16 * 80) + kof + TILE_B;
                uint32_t r0, r1, r2, r3;
                LDMX4(r0, r1, r2, r3, bd);
                bl[2 * p][0] = r0; bl[2 * p + 1][0] = r1;
                bl[2 * p][1] = r2; bl[2 * p + 1][1] = r3;
            }
#pragma unroll
            for (int mt = 0; mt < 4; ++mt)
#pragma unroll
                for (int nt = 0; nt < 4; ++nt)
                    MMA16816(&acc[(mt * 4 + nt) * 4], ah[mt], bl[nt]);
#pragma unroll
            for (int mt = 0; mt < 4; ++mt) {
                uint32_t ad = aBase + mt * (16 * 80) + kof + TILE_B;
                LDMX4(al[mt][0], al[mt][1], al[mt][2], al[mt][3], ad);
            }
#pragma unroll
            for (int mt = 0; mt < 4; ++mt)
#pragma unroll
                for (int nt = 0; nt < 4; ++nt)
                    MMA16816(&acc[(mt * 4 + nt) * 4], al[mt], bh[nt]);
        }
    };

    ISSUE(0);
    CPA_COMMIT();
    for (int t = 0; t < 32; ++t) {
        CPA_WAIT0();
        __syncthreads();
        if (t + 1 < 32) {
            ISSUE(t + 1);
            CPA_COMMIT();
        }
        COMPUTE(t & 1);

        if ((t & 7) == 7) {               // registers + const global only
            const int ct = t >> 3;
#pragma unroll
            for (int nt = 0; nt < 4; ++nt)
#pragma unroll
                for (int j = 0; j < 2; ++j) {
                    int col = ct * 128 + warpCol * 32 + nt * 8 + tig * 2 + j;
                    float c2v = g_c2[col];
#pragma unroll
                    for (int mt = 0; mt < 4; ++mt)
#pragma unroll
                        for (int h = 0; h < 2; ++h) {
                            float s = (c2v + e2r[mt * 2 + h]) -
                                2.0f * (acc[(mt * 4 + nt) * 4 + h * 2 + j] * OSCALE);
                            int bi = mt * 2 + h;
                            if (s < bestV[bi] ||
                                (s == bestV[bi] && col < bestI[bi])) {
                                bestV[bi] = s; bestI[bi] = col;
                            }
                        }
                }
#pragma unroll
            for (int i = 0; i < 64; ++i) acc[i] = 0.0f;
        }
    }
    __syncthreads();

    // ---- cross-thread reduction (16 slots per row) + fused count
    float (*rv)[16] = reinterpret_cast<float(*)[16]>(smem);
    int   (*ri)[16] = reinterpret_cast<int(*)[16]>(smem + 8192);
    const int slot = warpCol * 4 + tig;
#pragma unroll
    for (int mt = 0; mt < 4; ++mt)
#pragma unroll
        for (int h = 0; h < 2; ++h) {
            int row = warpRow * 64 + mt * 16 + g + h * 8;
            rv[row][slot] = bestV[mt * 2 + h];
            ri[row][slot] = bestI[mt * 2 + h];
        }
    __syncthreads();
    if (tid < 128) {
        float bv = rv[tid][0]; int bi = ri[tid][0];
#pragma unroll
        for (int u = 1; u < 16; ++u) {
            float v = rv[tid][u]; int ix = ri[tid][u];
            if (v < bv || (v == bv && ix < bi)) { bv = v; bi = ix; }
        }
        g_sc[modal * NTOK + rowBase + tid] = bi;
        atomicAdd(&g_counts[modal * KC + bi], 1);
    }
}

// ---------------------------------------------------------------------------
// emb fp32 -> (hi, lo) halves, scaled — both modals (y = modal)
// ---------------------------------------------------------------------------
__global__ void split_src(const float* __restrict__ X0,
                          const float* __restrict__ X1,
                          half* __restrict__ XhG, half* __restrict__ XlG)
{
    const int m = blockIdx.y;
    const float* X = m ? X1 : X0;
    half* Xh = XhG + (size_t)m * ASLAB;
    half* Xl = XlG + (size_t)m * ASLAB;
    int i = blockIdx.x * blockDim.x + threadIdx.x;
    float4 v = reinterpret_cast<const float4*>(X)[i];
    half h0, h1, h2, h3, l0, l1, l2, l3;
    split2(v.x * SCALE_A, h0, l0); split2(v.y * SCALE_A, h1, l1);
    split2(v.z * SCALE_A, h2, l2); split2(v.w * SCALE_A, h3, l3);
    half2 ph0 = __halves2half2(h0, h1), ph1 = __halves2half2(h2, h3);
    half2 pl0 = __halves2half2(l0, l1), pl1 = __halves2half2(l2, l3);
    uint2 uh, ul;
    uh.x = reinterpret_cast<uint32_t&>(ph0); uh.y = reinterpret_cast<uint32_t&>(ph1);
    ul.x = reinterpret_cast<uint32_t&>(pl0); ul.y = reinterpret_cast<uint32_t&>(pl1);
    reinterpret_cast<uint2*>(Xh)[i] = uh;
    reinterpret_cast<uint2*>(Xl)[i] = ul;
}

// ---------------------------------------------------------------------------
// All 6 weight transposes + splits in one launch.
// ---------------------------------------------------------------------------
__global__ void transpose_split_all(
    const float* __restrict__ W10, const float* __restrict__ W20,
    const float* __restrict__ W30, const float* __restrict__ W11,
    const float* __restrict__ W21, const float* __restrict__ W31)
{
    const int z = blockIdx.z;
    const int m = z / 3, layer = z % 3;
    const int N = (layer == 2) ? SEND : HIDD;
    if ((blockIdx.x << 5) >= N) return;

    const float* W =
        (layer == 0) ? (m ? W11 : W10) :
        (layer == 1) ? (m ? W21 : W20) : (m ? W31 : W30);
    half* Th = (layer == 0) ? g_w1h[m] : (layer == 1) ? g_w2h[m] : g_w3h[m];
    half* Tl = (layer == 0) ? g_w1l[m] : (layer == 1) ? g_w2l[m] : g_w3l[m];

    __shared__ float t[32][33];
    const int bx = blockIdx.x << 5;   // n base
    const int by = blockIdx.y << 5;   // k base
#pragma unroll
    for (int j = 0; j < 32; j += 8)
        t[threadIdx.y + j][threadIdx.x] =
            W[(size_t)(by + threadIdx.y + j) * N + bx + threadIdx.x];
    __syncthreads();
#pragma unroll
    for (int j = 0; j < 32; j += 8) {
        float f = t[threadIdx.x][threadIdx.y + j] * SCALE_B;
        half h, l;
        split2(f, h, l);
        size_t o = (size_t)(bx + threadIdx.y + j) * HIDD + by + threadIdx.x;
        Th[o] = h;
        Tl[o] = l;
    }
}

// ---------------------------------------------------------------------------
// Fused centroid prep: tanh -> d_out, split halves, c2 sumsq, zero counts.
// ---------------------------------------------------------------------------
__global__ void centroid_prep(const float* __restrict__ raw, float* __restrict__ out)
{
    const int tid  = threadIdx.x;
    const int lane = tid & 31;
    const int row  = blockIdx.x * 8 + (tid >> 5);
    const int gtid = blockIdx.x * 256 + tid;
    if (gtid < 2 * KC) g_counts[gtid] = 0;

    const float* src = raw + (size_t)row * SEND;
    float ss = 0.0f;
#pragma unroll
    for (int j = 0; j < 8; ++j) {
        int idx = lane + j * 32;
        float t = tanhf(src[idx]);
        out[CENT_OFF + (size_t)row * SEND + idx] = t;
        half h, l;
        split2(t * SCALE_B, h, l);
        g_ch[(size_t)row * SEND + idx] = h;
        g_cl[(size_t)row * SEND + idx] = l;
        ss = fmaf(t, t, ss);
    }
#pragma unroll
    for (int o = 16; o > 0; o >>= 1) ss += __shfl_xor_sync(0xffffffffu, ss, o);
    if (lane == 0) g_c2[row] = ss;
}

// ---------------------------------------------------------------------------
// Counting sort (stable) — both modals per launch
// ---------------------------------------------------------------------------
__global__ void scan_kernel()
{
    __shared__ int tmp[KC];
    const int modal = blockIdx.x;
    int t = threadIdx.x;
    int v = g_counts[modal * KC + t];
    tmp[t] = v;
    __syncthreads();
    for (int off = 1; off < KC; off <<= 1) {
        int x = (t >= off) ? tmp[t - off] : 0;
        __syncthreads();
        tmp[t] += x;
        __syncthreads();
    }
    g_offsets[modal * KC + t] = tmp[t] - v;
}

__global__ void scatter_kernel(float* __restrict__ out)
{
    const int k = blockIdx.x;
    const int modal = blockIdx.y;
    float* order = out + (modal ? OI_OFF : OT_OFF);
    const int base0 = modal * NTOK;
    __shared__ int warpTot[8];
    int base = g_offsets[modal * KC + k];
    int lane = threadIdx.x & 31, wid = threadIdx.x >> 5;

    for (int start = 0; start < NTOK; start += 256) {
        int i = start + threadIdx.x;
        bool m = (g_sc[base0 + i] == k);
        unsigned b = __ballot_sync(0xffffffffu, m);
        if (lane == 0) warpTot[wid] = __popc(b);
        __syncthreads();
        int woff = 0, tot = 0;
#pragma unroll
        for (int w = 0; w < 8; ++w) { int c = warpTot[w]; tot += c; if (w < wid) woff += c; }
        if (m) order[base + woff + __popc(b & ((1u << lane) - 1u))] = (float)i;
        base += tot;
        __syncthreads();
    }
}

// ---------------------------------------------------------------------------
// word_class / sense_class / counts (fused)
// ---------------------------------------------------------------------------
__global__ void finalize_kernel(float* __restrict__ out)
{
    int i = blockIdx.x * blockDim.x + threadIdx.x;
    out[WC_OFF + i]  = (i < NTOK) ? 0.0f : 1.0f;
    out[SCL_OFF + i] = (float)g_sc[i];
    if (i < 2 * KC) {
        int m = i >> 9, k = i & 511;
        out[(m ? CI_OFF : CT_OFF) + k] = (float)g_counts[i];
    }
}

// ---------------------------------------------------------------------------
// Launch
// ---------------------------------------------------------------------------
extern "C" void kernel_launch(void* const* d_in, const int* in_sizes, int n_in,
                              void* d_out, int out_size)
{
    const float* emb[2] = { (const float*)d_in[0], (const float*)d_in[1] };
    const float* W1[2]  = { (const float*)d_in[2], (const float*)d_in[5] };
    const float* W2[2]  = { (const float*)d_in[3], (const float*)d_in[6] };
    const float* W3[2]  = { (const float*)d_in[4], (const float*)d_in[7] };
    const float* craw   = (const float*)d_in[8];
    float* out = (float*)d_out;

    half *xh1, *xl1, *xh2, *xl2;
    half *w1h, *w1l, *w2h, *w2l, *w3h, *w3l;
    float* e2p;
    cudaGetSymbolAddress((void**)&xh1, g_xh1);
    cudaGetSymbolAddress((void**)&xl1, g_xl1);
    cudaGetSymbolAddress((void**)&xh2, g_xh2);
    cudaGetSymbolAddress((void**)&xl2, g_xl2);
    cudaGetSymbolAddress((void**)&w1h, g_w1h);
    cudaGetSymbolAddress((void**)&w1l, g_w1l);
    cudaGetSymbolAddress((void**)&w2h, g_w2h);
    cudaGetSymbolAddress((void**)&w2l, g_w2l);
    cudaGetSymbolAddress((void**)&w3h, g_w3h);
    cudaGetSymbolAddress((void**)&w3l, g_w3l);
    cudaGetSymbolAddress((void**)&e2p, g_e2p);

    cudaFuncSetAttribute(gemm_split<1>,
                         cudaFuncAttributeMaxDynamicSharedMemorySize, GEMM_SMEM);
    cudaFuncSetAttribute(gemm_split<2>,
                         cudaFuncAttributeMaxDynamicSharedMemorySize, GEMM_SMEM);
    cudaFuncSetAttribute(assign_mma,
                         cudaFuncAttributeMaxDynamicSharedMemorySize, ASSIGN_SMEM);

    const size_t WSZ  = (size_t)HIDD * HIDD;
    const size_t W3SZ = (size_t)SEND * HIDD;

    centroid_prep<<<KC / 8, 256>>>(craw, out);
    transpose_split_all<<<dim3(32, 32, 6), dim3(32, 8)>>>(
        W1[0], W2[0], W3[0], W1[1], W2[1], W3[1]);

    split_src<<<dim3((NTOK * TOKD / 4) / 256, 2), 256>>>(emb[0], emb[1], xh1, xl1);

    // L1: xh1 -> xh2 (both modals)
    gemm_split<1><<<dim3(HIDD / 128, NTOK / 128, 2), 256, GEMM_SMEM>>>(
        xh1, xl1, ASLAB, w1h, w1l, WSZ,
        nullptr, 0, xh2, xl2, ASLAB, nullptr, TOKD, HIDD);

    // L2: xh2 -> xh1
    gemm_split<1><<<dim3(HIDD / 128, NTOK / 128, 2), 256, GEMM_SMEM>>>(
        xh2, xl2, ASLAB, w2h, w2l, WSZ,
        nullptr, 0, xh1, xl1, ASLAB, nullptr, HIDD, HIDD);

    // L3: xh1 -> se (fp32) + xh2 (split) + e2 partials
    gemm_split<2><<<dim3(SEND / 128, NTOK / 128, 2), 256, GEMM_SMEM>>>(
        xh1, xl1, ASLAB, w3h, w3l, W3SZ,
        out + SE_OFF, (size_t)NTOK * SEND, xh2, xl2, ASLAB, e2p, HIDD, SEND);

    assign_mma<<<dim3(NTOK / 128, 2), 256, ASSIGN_SMEM>>>(xh2, xl2);

    scan_kernel<<<2, KC>>>();
    scatter_kernel<<<dim3(KC, 2), 256>>>(out);

    finalize_kernel<<<(2 * NTOK) / 256, 256>>>(out);
}

// round 17
// speedup vs baseline: 1.1153x; 1.0967x over previous
#include <cuda_runtime.h>
#include <cuda_fp16.h>
#include <math.h>
#include <stdint.h>

// ---------------------------------------------------------------------------
// Problem constants
// ---------------------------------------------------------------------------
#define NTOK 32768
#define TOKD 1024
#define HIDD 1024
#define SEND 256
#define KC   512

// d_out float offsets (flattened reference tuple, fp32)
#define CENT_OFF 0
#define SE_OFF   131072
#define WC_OFF   16908288
#define SCL_OFF  16973824
#define OT_OFF   17039360
#define CT_OFF   17072128
#define OI_OFF   17072640
#define CI_OFF   17105408

#define SCALE_A 16.0f
#define SCALE_B 64.0f
#define OSCALE  (1.0f / 1024.0f)

#define ASLAB ((size_t)NTOK * HIDD)      // per-modal activation slab (elements)

// ---------------------------------------------------------------------------
// Scratch (device globals) — per-modal activation slabs for merged launches
// ---------------------------------------------------------------------------
__device__ half  g_xh1[2][ASLAB];
__device__ half  g_xl1[2][ASLAB];
__device__ half  g_xh2[2][ASLAB];
__device__ half  g_xl2[2][ASLAB];
__device__ half  g_w1h[2][(size_t)HIDD * HIDD];   // transposed weights, N-major
__device__ half  g_w1l[2][(size_t)HIDD * HIDD];
__device__ half  g_w2h[2][(size_t)HIDD * HIDD];
__device__ half  g_w2l[2][(size_t)HIDD * HIDD];
__device__ half  g_w3h[2][(size_t)SEND * HIDD];
__device__ half  g_w3l[2][(size_t)SEND * HIDD];
__device__ half  g_ch[(size_t)KC * SEND];         // centroids hi (x64)
__device__ half  g_cl[(size_t)KC * SEND];         // centroids lo
__device__ float g_c2[KC];
__device__ float g_e2p[4 * NTOK];                 // [plane(2)][modal(2)][NTOK]
__device__ int   g_sc[2 * NTOK];
__device__ int   g_counts[2 * KC];

// ---------------------------------------------------------------------------
// PTX helpers (sm_80-era, portable under compute_100)
// ---------------------------------------------------------------------------
__device__ __forceinline__ uint32_t smem_u32(const void* p) {
    uint32_t a;
    asm("{ .reg .u64 t; cvta.to.shared.u64 t, %1; cvt.u32.u64 %0, t; }"
        : "=r"(a) : "l"(p));
    return a;
}

#define MMA16816(d, a, b) \
    asm volatile( \
        "mma.sync.aligned.m16n8k16.row.col.f32.f16.f16.f32 " \
        "{%0,%1,%2,%3}, {%4,%5,%6,%7}, {%8,%9}, {%0,%1,%2,%3};" \
        : "+f"((d)[0]), "+f"((d)[1]), "+f"((d)[2]), "+f"((d)[3]) \
        : "r"((a)[0]), "r"((a)[1]), "r"((a)[2]), "r"((a)[3]), \
          "r"((b)[0]), "r"((b)[1]))

#define LDMX4(r0, r1, r2, r3, addr) \
    asm volatile("ldmatrix.sync.aligned.m8n8.x4.shared.b16 {%0,%1,%2,%3}, [%4];" \
        : "=r"(r0), "=r"(r1), "=r"(r2), "=r"(r3) : "r"(addr))

// cp.async.ca — L1-allocating. Fills have real L1 reuse (weight tiles shared
// by all row-band CTAs, A tiles by column-band CTAs); .cg measured slower.
#define CPA16(dst, src) \
    asm volatile("cp.async.ca.shared.global [%0], [%1], 16;" :: "r"(dst), "l"(src))
#define CPA_COMMIT() asm volatile("cp.async.commit_group;")
#define CPA_WAIT0()  asm volatile("cp.async.wait_group 0;")

__device__ __forceinline__ void split2(float f, half& h, half& l) {
    h = __float2half_rn(f);
    l = __float2half_rn(f - __half2float(h));
}

// ---------------------------------------------------------------------------
// fp16x3 split-GEMM, both modals per launch (z = modal).
// Single-sync mainloop; COMPUTE interleaves fragment loads with MMA groups
// (group order ah*bh, ah*bl, al*bh preserved -> bit-identical accumulation).
// OMODE: 1 = split (hi,lo)*SCALE_A out; 2 = fp32 out + split out + e2 partials.
// ---------------------------------------------------------------------------
#define TILE_B    10240         // 128 rows * 80 B
#define STAGE_B   40960         // Ah | Al | Bh | Bl tiles
#define GEMM_SMEM 81920         // 2 stages

template<int OMODE>
__global__ __launch_bounds__(256)
void gemm_split(const half* __restrict__ AhG, const half* __restrict__ AlG,
                size_t aStr,
                const half* __restrict__ BhG, const half* __restrict__ BlG,
                size_t bStr,
                float* __restrict__ CfG, size_t cfStr,
                half* __restrict__ CohG, half* __restrict__ ColG, size_t coStr,
                float* __restrict__ E2p,
                int Kdim, int Mcols)
{
    extern __shared__ __align__(16) char smem[];
    const uint32_t sb0 = smem_u32(smem);

    const int z = blockIdx.z;
    const half* Ah = AhG + (size_t)z * aStr;
    const half* Al = AlG + (size_t)z * aStr;
    const half* Bh = BhG + (size_t)z * bStr;
    const half* Bl = BlG + (size_t)z * bStr;

    const int tid  = threadIdx.x;
    const int lane = tid & 31, wid = tid >> 5;
    const int warpRow = wid >> 2;
    const int warpCol = wid & 3;
    const int g = lane >> 2, tig = lane & 3;
    const int blockRow = blockIdx.y << 7;
    const int blockCol = blockIdx.x << 7;

    float acc[64];
#pragma unroll
    for (int i = 0; i < 64; ++i) acc[i] = 0.0f;

    const int fr = tid >> 1;
    const int fb = (tid & 1) << 1;
    const half* srcA  = Ah + (size_t)(blockRow + fr) * Kdim + fb * 8;
    const half* srcAl = Al + (size_t)(blockRow + fr) * Kdim + fb * 8;
    const half* srcB  = Bh + (size_t)(blockCol + fr) * Kdim + fb * 8;
    const half* srcBl = Bl + (size_t)(blockCol + fr) * Kdim + fb * 8;
    const uint32_t dstBase = sb0 + fr * 80 + fb * 16;

    const uint32_t loff = (uint32_t)(((lane & 7) + ((lane >> 3) & 1) * 8) * 80
                                     + ((lane >> 4) & 1) * 16);

    const int chunks = Kdim >> 5;

    auto ISSUE = [&](int c) {
        const int s = c & 1;
        const int kh = c << 5;
        uint32_t d = dstBase + s * STAGE_B;
        CPA16(d,              srcA + kh);  CPA16(d + 16,              srcA + kh + 8);
        CPA16(d + TILE_B,     srcAl + kh); CPA16(d + TILE_B + 16,     srcAl + kh + 8);
        CPA16(d + 2 * TILE_B, srcB + kh);  CPA16(d + 2 * TILE_B + 16, srcB + kh + 8);
        CPA16(d + 3 * TILE_B, srcBl + kh); CPA16(d + 3 * TILE_B + 16, srcBl + kh + 8);
    };

    auto COMPUTE = [&](int s) {
        const uint32_t base  = sb0 + s * STAGE_B;
        const uint32_t aBase = base + (warpRow * 64) * 80 + loff;
        const uint32_t bBase = base + 2 * TILE_B + (warpCol * 32) * 80 + loff;
#pragma unroll
        for (int ks = 0; ks < 2; ++ks) {
            const uint32_t kof = ks << 5;
            uint32_t ah[4][4], al[4][4], bh[4][2], bl[4][2];
            // -- load ah + bh, run group 1 (ah*bh)
#pragma unroll
            for (int mt = 0; mt < 4; ++mt) {
                uint32_t ad = aBase + mt * (16 * 80) + kof;
                LDMX4(ah[mt][0], ah[mt][1], ah[mt][2], ah[mt][3], ad);
            }
#pragma unroll
            for (int p = 0; p < 2; ++p) {
                uint32_t bd = bBase + p * (16 * 80) + kof;
                uint32_t r0, r1, r2, r3;
                LDMX4(r0, r1, r2, r3, bd);
                bh[2 * p][0] = r0; bh[2 * p + 1][0] = r1;
                bh[2 * p][1] = r2; bh[2 * p + 1][1] = r3;
            }
#pragma unroll
            for (int mt = 0; mt < 4; ++mt)
#pragma unroll
                for (int nt = 0; nt < 4; ++nt)
                    MMA16816(&acc[(mt * 4 + nt) * 4], ah[mt], bh[nt]);
            // -- load bl, run group 2 (ah*bl)
#pragma unroll
            for (int p = 0; p < 2; ++p) {
                uint32_t bd = bBase + p * (16 * 80) + kof + TILE_B;
                uint32_t r0, r1, r2, r3;
                LDMX4(r0, r1, r2, r3, bd);
                bl[2 * p][0] = r0; bl[2 * p + 1][0] = r1;
                bl[2 * p][1] = r2; bl[2 * p + 1][1] = r3;
            }
#pragma unroll
            for (int mt = 0; mt < 4; ++mt)
#pragma unroll
                for (int nt = 0; nt < 4; ++nt)
                    MMA16816(&acc[(mt * 4 + nt) * 4], ah[mt], bl[nt]);
            // -- load al, run group 3 (al*bh)
#pragma unroll
            for (int mt = 0; mt < 4; ++mt) {
                uint32_t ad = aBase + mt * (16 * 80) + kof + TILE_B;
                LDMX4(al[mt][0], al[mt][1], al[mt][2], al[mt][3], ad);
            }
#pragma unroll
            for (int mt = 0; mt < 4; ++mt)
#pragma unroll
                for (int nt = 0; nt < 4; ++nt)
                    MMA16816(&acc[(mt * 4 + nt) * 4], al[mt], bh[nt]);
        }
    };

    ISSUE(0);
    CPA_COMMIT();
    for (int c = 0; c < chunks; ++c) {
        CPA_WAIT0();
        __syncthreads();          // chunk c visible; stage (c+1)&1 free
        if (c + 1 < chunks) {
            ISSUE(c + 1);
            CPA_COMMIT();
        }
        COMPUTE(c & 1);
    }
    __syncthreads();

    // ---- epilogue: stage fp32 acc in smem, then coalesced transform+store
    float* cst = reinterpret_cast<float*>(smem);   // [128][132]
#pragma unroll
    for (int mt = 0; mt < 4; ++mt)
#pragma unroll
        for (int nt = 0; nt < 4; ++nt) {
            const float* a4 = &acc[(mt * 4 + nt) * 4];
            int r0 = (warpRow << 6) + (mt << 4) + g;
            int cc = (warpCol << 5) + (nt << 3) + (tig << 1);
            *reinterpret_cast<float2*>(cst + r0 * 132 + cc) =
                make_float2(a4[0], a4[1]);
            *reinterpret_cast<float2*>(cst + (r0 + 8) * 132 + cc) =
                make_float2(a4[2], a4[3]);
        }
    __syncthreads();
    {
        half*  Coh = CohG + (size_t)z * coStr;
        half*  Col = ColG + (size_t)z * coStr;
        const int row  = tid >> 1;
        const int colh = (tid & 1) << 6;
        const float* src = cst + row * 132 + colh;
        const size_t gb = (size_t)(blockRow + row) * Mcols + blockCol + colh;
        float ss = 0.0f;
#pragma unroll
        for (int j = 0; j < 16; ++j) {
            float4 v = *reinterpret_cast<const float4*>(src + (j << 2));
            float t0 = tanhf(v.x * OSCALE), t1 = tanhf(v.y * OSCALE);
            float t2 = tanhf(v.z * OSCALE), t3 = tanhf(v.w * OSCALE);
            if (OMODE >= 1) {
                half h0, h1, h2, h3, l0, l1, l2, l3;
                split2(t0 * SCALE_A, h0, l0); split2(t1 * SCALE_A, h1, l1);
                split2(t2 * SCALE_A, h2, l2); split2(t3 * SCALE_A, h3, l3);
                half2 ph0 = __halves2half2(h0, h1), ph1 = __halves2half2(h2, h3);
                half2 pl0 = __halves2half2(l0, l1), pl1 = __halves2half2(l2, l3);
                uint2 uh, ul;
                uh.x = reinterpret_cast<uint32_t&>(ph0);
                uh.y = reinterpret_cast<uint32_t&>(ph1);
                ul.x = reinterpret_cast<uint32_t&>(pl0);
                ul.y = reinterpret_cast<uint32_t&>(pl1);
                *reinterpret_cast<uint2*>(Coh + gb + (j << 2)) = uh;
                *reinterpret_cast<uint2*>(Col + gb + (j << 2)) = ul;
            }
            if (OMODE == 2) {
                ss = fmaf(t0, t0, ss); ss = fmaf(t1, t1, ss);
                ss = fmaf(t2, t2, ss); ss = fmaf(t3, t3, ss);
                float4 o; o.x = t0; o.y = t1; o.z = t2; o.w = t3;
                *reinterpret_cast<float4*>(CfG + (size_t)z * cfStr + gb + (j << 2)) = o;
            }
        }
        if (OMODE == 2) {
            float* e2s = reinterpret_cast<float*>(smem) + 16896;   // past cst
            e2s[tid] = ss;
            __syncthreads();
            if ((tid & 1) == 0)
                E2p[(size_t)blockIdx.x * (2 * NTOK) + (size_t)z * NTOK
                    + blockRow + (tid >> 1)] = e2s[tid] + e2s[tid + 1];
        }
    }
}

// ---------------------------------------------------------------------------
// Tensor-core assignment, both modals (y = modal); fused count.
// ---------------------------------------------------------------------------
#define ASSIGN_SMEM 81920

__global__ __launch_bounds__(256)
void assign_mma(const half* __restrict__ ShG, const half* __restrict__ SlG)
{
    extern __shared__ __align__(16) char smem[];
    const uint32_t sb0 = smem_u32(smem);
    const int modal = blockIdx.y;
    const half* Sh = ShG + (size_t)modal * ASLAB;
    const half* Sl = SlG + (size_t)modal * ASLAB;

    const int tid  = threadIdx.x;
    const int lane = tid & 31, wid = tid >> 5;
    const int warpRow = wid >> 2, warpCol = wid & 3;
    const int g = lane >> 2, tig = lane & 3;
    const int rowBase = blockIdx.x << 7;

    const int fr = tid >> 1, fb = (tid & 1) << 1;
    const half* pAh = Sh + (size_t)(rowBase + fr) * SEND + fb * 8;
    const half* pAl = Sl + (size_t)(rowBase + fr) * SEND + fb * 8;
    const uint32_t dAB = sb0 + fr * 80 + fb * 16;

    const uint32_t loff = (uint32_t)(((lane & 7) + ((lane >> 3) & 1) * 8) * 80
                                     + ((lane >> 4) & 1) * 16);

    float e2r[8];
#pragma unroll
    for (int mt = 0; mt < 4; ++mt)
#pragma unroll
        for (int h = 0; h < 2; ++h) {
            int idx = modal * NTOK + rowBase + warpRow * 64 + mt * 16 + g + h * 8;
            e2r[mt * 2 + h] = g_e2p[idx] + g_e2p[2 * NTOK + idx];
        }

    float bestV[8]; int bestI[8];
#pragma unroll
    for (int i = 0; i < 8; ++i) { bestV[i] = 3.4e38f; bestI[i] = 0; }

    float acc[64];
#pragma unroll
    for (int i = 0; i < 64; ++i) acc[i] = 0.0f;

    auto ISSUE = [&](int t) {
        const int ct = t >> 3, c = t & 7;
        const int kh = c << 5;
        uint32_t d = dAB + (uint32_t)(t & 1) * STAGE_B;
        CPA16(d,              pAh + kh); CPA16(d + 16,              pAh + kh + 8);
        CPA16(d + TILE_B,     pAl + kh); CPA16(d + TILE_B + 16,     pAl + kh + 8);
        const half* pBh = g_ch + (size_t)(ct * 128 + fr) * SEND + fb * 8 + kh;
        const half* pBl = g_cl + (size_t)(ct * 128 + fr) * SEND + fb * 8 + kh;
        CPA16(d + 2 * TILE_B, pBh);      CPA16(d + 2 * TILE_B + 16, pBh + 8);
        CPA16(d + 3 * TILE_B, pBl);      CPA16(d + 3 * TILE_B + 16, pBl + 8);
    };

    auto COMPUTE = [&](int s) {
        const uint32_t base  = sb0 + s * STAGE_B;
        const uint32_t aBase = base + (warpRow * 64) * 80 + loff;
        const uint32_t bBase = base + 2 * TILE_B + (warpCol * 32) * 80 + loff;
#pragma unroll
        for (int ks = 0; ks < 2; ++ks) {
            const uint32_t kof = ks << 5;
            uint32_t ah[4][4], al[4][4], bh[4][2], bl[4][2];
#pragma unroll
            for (int mt = 0; mt < 4; ++mt) {
                uint32_t ad = aBase + mt * (16 * 80) + kof;
                LDMX4(ah[mt][0], ah[mt][1], ah[mt][2], ah[mt][3], ad);
            }
#pragma unroll
            for (int p = 0; p < 2; ++p) {
                uint32_t bd = bBase + p * (16 * 80) + kof;
                uint32_t r0, r1, r2, r3;
                LDMX4(r0, r1, r2, r3, bd);
                bh[2 * p][0] = r0; bh[2 * p + 1][0] = r1;
                bh[2 * p][1] = r2; bh[2 * p + 1][1] = r3;
            }
#pragma unroll
            for (int mt = 0; mt < 4; ++mt)
#pragma unroll
                for (int nt = 0; nt < 4; ++nt)
                    MMA16816(&acc[(mt * 4 + nt) * 4], ah[mt], bh[nt]);
#pragma unroll
            for (int p = 0; p < 2; ++p) {
                uint32_t bd = bBase + p * (16 * 80) + kof + TILE_B;
                uint32_t r0, r1, r2, r3;
                LDMX4(r0, r1, r2, r3, bd);
                bl[2 * p][0] = r0; bl[2 * p + 1][0] = r1;
                bl[2 * p][1] = r2; bl[2 * p + 1][1] = r3;
            }
#pragma unroll
            for (int mt = 0; mt < 4; ++mt)
#pragma unroll
                for (int nt = 0; nt < 4; ++nt)
                    MMA16816(&acc[(mt * 4 + nt) * 4], ah[mt], bl[nt]);
#pragma unroll
            for (int mt = 0; mt < 4; ++mt) {
                uint32_t ad = aBase + mt * (16 * 80) + kof + TILE_B;
                LDMX4(al[mt][0], al[mt][1], al[mt][2], al[mt][3], ad);
            }
#pragma unroll
            for (int mt = 0; mt < 4; ++mt)
#pragma unroll
                for (int nt = 0; nt < 4; ++nt)
                    MMA16816(&acc[(mt * 4 + nt) * 4], al[mt], bh[nt]);
        }
    };

    ISSUE(0);
    CPA_COMMIT();
    for (int t = 0; t < 32; ++t) {
        CPA_WAIT0();
        __syncthreads();
        if (t + 1 < 32) {
            ISSUE(t + 1);
            CPA_COMMIT();
        }
        COMPUTE(t & 1);

        if ((t & 7) == 7) {               // registers + const global only
            const int ct = t >> 3;
#pragma unroll
            for (int nt = 0; nt < 4; ++nt)
#pragma unroll
                for (int j = 0; j < 2; ++j) {
                    int col = ct * 128 + warpCol * 32 + nt * 8 + tig * 2 + j;
                    float c2v = g_c2[col];
#pragma unroll
                    for (int mt = 0; mt < 4; ++mt)
#pragma unroll
                        for (int h = 0; h < 2; ++h) {
                            float s = (c2v + e2r[mt * 2 + h]) -
                                2.0f * (acc[(mt * 4 + nt) * 4 + h * 2 + j] * OSCALE);
                            int bi = mt * 2 + h;
                            if (s < bestV[bi] ||
                                (s == bestV[bi] && col < bestI[bi])) {
                                bestV[bi] = s; bestI[bi] = col;
                            }
                        }
                }
#pragma unroll
            for (int i = 0; i < 64; ++i) acc[i] = 0.0f;
        }
    }
    __syncthreads();

    // ---- cross-thread reduction (16 slots per row) + fused count
    float (*rv)[16] = reinterpret_cast<float(*)[16]>(smem);
    int   (*ri)[16] = reinterpret_cast<int(*)[16]>(smem + 8192);
    const int slot = warpCol * 4 + tig;
#pragma unroll
    for (int mt = 0; mt < 4; ++mt)
#pragma unroll
        for (int h = 0; h < 2; ++h) {
            int row = warpRow * 64 + mt * 16 + g + h * 8;
            rv[row][slot] = bestV[mt * 2 + h];
            ri[row][slot] = bestI[mt * 2 + h];
        }
    __syncthreads();
    if (tid < 128) {
        float bv = rv[tid][0]; int bi = ri[tid][0];
#pragma unroll
        for (int u = 1; u < 16; ++u) {
            float v = rv[tid][u]; int ix = ri[tid][u];
            if (v < bv || (v == bv && ix < bi)) { bv = v; bi = ix; }
        }
        g_sc[modal * NTOK + rowBase + tid] = bi;
        atomicAdd(&g_counts[modal * KC + bi], 1);
    }
}

// ---------------------------------------------------------------------------
// emb fp32 -> (hi, lo) halves, scaled — both modals (y = modal)
// ---------------------------------------------------------------------------
__global__ void split_src(const float* __restrict__ X0,
                          const float* __restrict__ X1,
                          half* __restrict__ XhG, half* __restrict__ XlG)
{
    const int m = blockIdx.y;
    const float* X = m ? X1 : X0;
    half* Xh = XhG + (size_t)m * ASLAB;
    half* Xl = XlG + (size_t)m * ASLAB;
    int i = blockIdx.x * blockDim.x + threadIdx.x;
    float4 v = reinterpret_cast<const float4*>(X)[i];
    half h0, h1, h2, h3, l0, l1, l2, l3;
    split2(v.x * SCALE_A, h0, l0); split2(v.y * SCALE_A, h1, l1);
    split2(v.z * SCALE_A, h2, l2); split2(v.w * SCALE_A, h3, l3);
    half2 ph0 = __halves2half2(h0, h1), ph1 = __halves2half2(h2, h3);
    half2 pl0 = __halves2half2(l0, l1), pl1 = __halves2half2(l2, l3);
    uint2 uh, ul;
    uh.x = reinterpret_cast<uint32_t&>(ph0); uh.y = reinterpret_cast<uint32_t&>(ph1);
    ul.x = reinterpret_cast<uint32_t&>(pl0); ul.y = reinterpret_cast<uint32_t&>(pl1);
    reinterpret_cast<uint2*>(Xh)[i] = uh;
    reinterpret_cast<uint2*>(Xl)[i] = ul;
}

// ---------------------------------------------------------------------------
// All 6 weight transposes + splits in one launch.
// ---------------------------------------------------------------------------
__global__ void transpose_split_all(
    const float* __restrict__ W10, const float* __restrict__ W20,
    const float* __restrict__ W30, const float* __restrict__ W11,
    const float* __restrict__ W21, const float* __restrict__ W31)
{
    const int z = blockIdx.z;
    const int m = z / 3, layer = z % 3;
    const int N = (layer == 2) ? SEND : HIDD;
    if ((blockIdx.x << 5) >= N) return;

    const float* W =
        (layer == 0) ? (m ? W11 : W10) :
        (layer == 1) ? (m ? W21 : W20) : (m ? W31 : W30);
    half* Th = (layer == 0) ? g_w1h[m] : (layer == 1) ? g_w2h[m] : g_w3h[m];
    half* Tl = (layer == 0) ? g_w1l[m] : (layer == 1) ? g_w2l[m] : g_w3l[m];

    __shared__ float t[32][33];
    const int bx = blockIdx.x << 5;   // n base
    const int by = blockIdx.y << 5;   // k base
#pragma unroll
    for (int j = 0; j < 32; j += 8)
        t[threadIdx.y + j][threadIdx.x] =
            W[(size_t)(by + threadIdx.y + j) * N + bx + threadIdx.x];
    __syncthreads();
#pragma unroll
    for (int j = 0; j < 32; j += 8) {
        float f = t[threadIdx.x][threadIdx.y + j] * SCALE_B;
        half h, l;
        split2(f, h, l);
        size_t o = (size_t)(bx + threadIdx.y + j) * HIDD + by + threadIdx.x;
        Th[o] = h;
        Tl[o] = l;
    }
}

// ---------------------------------------------------------------------------
// Fused centroid prep: tanh -> d_out, split halves, c2 sumsq, zero counts.
// ---------------------------------------------------------------------------
__global__ void centroid_prep(const float* __restrict__ raw, float* __restrict__ out)
{
    const int tid  = threadIdx.x;
    const int lane = tid & 31;
    const int row  = blockIdx.x * 8 + (tid >> 5);
    const int gtid = blockIdx.x * 256 + tid;
    if (gtid < 2 * KC) g_counts[gtid] = 0;

    const float* src = raw + (size_t)row * SEND;
    float ss = 0.0f;
#pragma unroll
    for (int j = 0; j < 8; ++j) {
        int idx = lane + j * 32;
        float t = tanhf(src[idx]);
        out[CENT_OFF + (size_t)row * SEND + idx] = t;
        half h, l;
        split2(t * SCALE_B, h, l);
        g_ch[(size_t)row * SEND + idx] = h;
        g_cl[(size_t)row * SEND + idx] = l;
        ss = fmaf(t, t, ss);
    }
#pragma unroll
    for (int o = 16; o > 0; o >>= 1) ss += __shfl_xor_sync(0xffffffffu, ss, o);
    if (lane == 0) g_c2[row] = ss;
}

// ---------------------------------------------------------------------------
// Stable counting-sort scatter with inline exclusive-prefix (scan fused):
// block (k, modal) sums counts[modal][0..k-1] itself, then ballot-compacts.
// ---------------------------------------------------------------------------
__global__ void scatter_kernel(float* __restrict__ out)
{
    const int k = blockIdx.x;
    const int modal = blockIdx.y;
    float* order = out + (modal ? OI_OFF : OT_OFF);
    const int base0 = modal * NTOK;
    __shared__ int warpTot[8];
    __shared__ int blockBase;

    int lane = threadIdx.x & 31, wid = threadIdx.x >> 5;

    // inline exclusive prefix of counts for this class
    {
        int p = 0;
        for (int j = threadIdx.x; j < k; j += 256) p += g_counts[modal * KC + j];
#pragma unroll
        for (int o = 16; o > 0; o >>= 1) p += __shfl_xor_sync(0xffffffffu, p, o);
        if (lane == 0) warpTot[wid] = p;
        __syncthreads();
        if (threadIdx.x == 0) {
            int s = 0;
#pragma unroll
            for (int w = 0; w < 8; ++w) s += warpTot[w];
            blockBase = s;
        }
        __syncthreads();
    }
    int base = blockBase;
    __syncthreads();          // warpTot reused below

    for (int start = 0; start < NTOK; start += 256) {
        int i = start + threadIdx.x;
        bool m = (g_sc[base0 + i] == k);
        unsigned b = __ballot_sync(0xffffffffu, m);
        if (lane == 0) warpTot[wid] = __popc(b);
        __syncthreads();
        int woff = 0, tot = 0;
#pragma unroll
        for (int w = 0; w < 8; ++w) { int c = warpTot[w]; tot += c; if (w < wid) woff += c; }
        if (m) order[base + woff + __popc(b & ((1u << lane) - 1u))] = (float)i;
        base += tot;
        __syncthreads();
    }
}

// ---------------------------------------------------------------------------
// word_class / sense_class / counts (fused)
// ---------------------------------------------------------------------------
__global__ void finalize_kernel(float* __restrict__ out)
{
    int i = blockIdx.x * blockDim.x + threadIdx.x;
    out[WC_OFF + i]  = (i < NTOK) ? 0.0f : 1.0f;
    out[SCL_OFF + i] = (float)g_sc[i];
    if (i < 2 * KC) {
        int m = i >> 9, k = i & 511;
        out[(m ? CI_OFF : CT_OFF) + k] = (float)g_counts[i];
    }
}

// ---------------------------------------------------------------------------
// Launch
// ---------------------------------------------------------------------------
extern "C" void kernel_launch(void* const* d_in, const int* in_sizes, int n_in,
                              void* d_out, int out_size)
{
    const float* emb[2] = { (const float*)d_in[0], (const float*)d_in[1] };
    const float* W1[2]  = { (const float*)d_in[2], (const float*)d_in[5] };
    const float* W2[2]  = { (const float*)d_in[3], (const float*)d_in[6] };
    const float* W3[2]  = { (const float*)d_in[4], (const float*)d_in[7] };
    const float* craw   = (const float*)d_in[8];
    float* out = (float*)d_out;

    half *xh1, *xl1, *xh2, *xl2;
    half *w1h, *w1l, *w2h, *w2l, *w3h, *w3l;
    float* e2p;
    cudaGetSymbolAddress((void**)&xh1, g_xh1);
    cudaGetSymbolAddress((void**)&xl1, g_xl1);
    cudaGetSymbolAddress((void**)&xh2, g_xh2);
    cudaGetSymbolAddress((void**)&xl2, g_xl2);
    cudaGetSymbolAddress((void**)&w1h, g_w1h);
    cudaGetSymbolAddress((void**)&w1l, g_w1l);
    cudaGetSymbolAddress((void**)&w2h, g_w2h);
    cudaGetSymbolAddress((void**)&w2l, g_w2l);
    cudaGetSymbolAddress((void**)&w3h, g_w3h);
    cudaGetSymbolAddress((void**)&w3l, g_w3l);
    cudaGetSymbolAddress((void**)&e2p, g_e2p);

    cudaFuncSetAttribute(gemm_split<1>,
                         cudaFuncAttributeMaxDynamicSharedMemorySize, GEMM_SMEM);
    cudaFuncSetAttribute(gemm_split<2>,
                         cudaFuncAttributeMaxDynamicSharedMemorySize, GEMM_SMEM);
    cudaFuncSetAttribute(assign_mma,
                         cudaFuncAttributeMaxDynamicSharedMemorySize, ASSIGN_SMEM);

    const size_t WSZ  = (size_t)HIDD * HIDD;
    const size_t W3SZ = (size_t)SEND * HIDD;

    centroid_prep<<<KC / 8, 256>>>(craw, out);
    transpose_split_all<<<dim3(32, 32, 6), dim3(32, 8)>>>(
        W1[0], W2[0], W3[0], W1[1], W2[1], W3[1]);

    split_src<<<dim3((NTOK * TOKD / 4) / 256, 2), 256>>>(emb[0], emb[1], xh1, xl1);

    // L1: xh1 -> xh2 (both modals)
    gemm_split<1><<<dim3(HIDD / 128, NTOK / 128, 2), 256, GEMM_SMEM>>>(
        xh1, xl1, ASLAB, w1h, w1l, WSZ,
        nullptr, 0, xh2, xl2, ASLAB, nullptr, TOKD, HIDD);

    // L2: xh2 -> xh1
    gemm_split<1><<<dim3(HIDD / 128, NTOK / 128, 2), 256, GEMM_SMEM>>>(
        xh2, xl2, ASLAB, w2h, w2l, WSZ,
        nullptr, 0, xh1, xl1, ASLAB, nullptr, HIDD, HIDD);

    // L3: xh1 -> se (fp32) + xh2 (split) + e2 partials
    gemm_split<2><<<dim3(SEND / 128, NTOK / 128, 2), 256, GEMM_SMEM>>>(
        xh1, xl1, ASLAB, w3h, w3l, W3SZ,
        out + SE_OFF, (size_t)NTOK * SEND, xh2, xl2, ASLAB, e2p, HIDD, SEND);

    assign_mma<<<dim3(NTOK / 128, 2), 256, ASSIGN_SMEM>>>(xh2, xl2);

    scatter_kernel<<<dim3(KC, 2), 256>>>(out);

    finalize_kernel<<<(2 * NTOK) / 256, 256>>>(out);
}